// round 10
// baseline (speedup 1.0000x reference)
#include <cuda_runtime.h>
#include <cuda_bf16.h>
#include <cstdint>
#include <math.h>

#define NN 8192
#define DD 256
#define KTOP 5
#define NC 32
#define PA 68
#define PB 132
#define SMEM_BYTES ((256 * PA + 256 * PB) * 4)
#define SMEMT_BYTES (SMEM_BYTES + (64 * 17 + 64) * 4)

#define HP 264                         // bf16 pitch (528B): conflict-free ldmatrix
#define ABYTES (128 * HP * 2)          // 67584 per tile buffer
#define AFF_SMEM (3 * ABYTES)          // A + B0 + B1 = 202752
#define PCC 129                        // C dump pitch (floats)

typedef unsigned long long ull;

// ---------------- scratch ----------------
__device__ float g_scale[DD];
__device__ float g_shift[DD];
__device__ float g_HnT[DD * NN];
__device__ float g_F1[NN * DD];
__device__ __nv_bfloat16 g_F1h[NN * DD];
__device__ float g_B[NN * DD];
__device__ int   g_ci[NN * NC];
__device__ int   g_topi[NN * KTOP];
__device__ float g_av[NN * KTOP];
__device__ float g_dinv[NN];

// ---------------- helpers ----------------
__device__ __forceinline__ ull dup_f(float a) {
    ull d; asm("mov.b64 %0, {%1, %1};" : "=l"(d) : "r"(__float_as_uint(a))); return d;
}
__device__ __forceinline__ void ffma2(ull& d, ull a, ull b) {
    asm("fma.rn.f32x2 %0, %1, %2, %0;" : "+l"(d) : "l"(a), "l"(b));
}
__device__ __forceinline__ float lo32(ull u) { return __uint_as_float((unsigned)u); }
__device__ __forceinline__ float hi32(ull u) { return __uint_as_float((unsigned)(u >> 32)); }

// bf16x2 -> f32x2 pair (lane0 = low bf16 = even-k, lane1 = high = odd-k)
__device__ __forceinline__ ull cvt_bf2(uint32_t u) {
    ull d;
    asm("{ .reg .b32 lo, hi; shl.b32 lo, %1, 16; and.b32 hi, %1, 0xFFFF0000; mov.b64 %0, {lo, hi}; }"
        : "=l"(d) : "r"(u));
    return d;
}

__device__ __forceinline__ uint32_t smem_u32(const void* p) {
    uint32_t a;
    asm("{ .reg .u64 t; cvta.to.shared.u64 t, %1; cvt.u32.u64 %0, t; }" : "=r"(a) : "l"(p));
    return a;
}
__device__ __forceinline__ void ldmx4(uint32_t* r, uint32_t addr) {
    asm volatile("ldmatrix.sync.aligned.m8n8.x4.shared.b16 {%0,%1,%2,%3}, [%4];"
        : "=r"(r[0]), "=r"(r[1]), "=r"(r[2]), "=r"(r[3]) : "r"(addr));
}
__device__ __forceinline__ void mma_bf16(float* d, const uint32_t* a,
                                         uint32_t b0, uint32_t b1) {
    asm volatile(
        "mma.sync.aligned.m16n8k16.row.col.f32.bf16.bf16.f32 "
        "{%0,%1,%2,%3}, {%4,%5,%6,%7}, {%8,%9}, {%0,%1,%2,%3};"
        : "+f"(d[0]), "+f"(d[1]), "+f"(d[2]), "+f"(d[3])
        : "r"(a[0]), "r"(a[1]), "r"(a[2]), "r"(a[3]), "r"(b0), "r"(b1));
}
#define CP16(dst, src) asm volatile("cp.async.ca.shared.global [%0], [%1], 16;" :: "r"(dst), "l"(src))
#define CP_COMMIT()    asm volatile("cp.async.commit_group;" ::: "memory")
#define CP_WAIT(n)     asm volatile("cp.async.wait_group %0;" :: "n"(n) : "memory")

__device__ __forceinline__ uint32_t lds32(uint32_t addr) {
    uint32_t v;
    asm volatile("ld.shared.b32 %0, [%1];" : "=r"(v) : "r"(addr));
    return v;
}

// stage 128x256 bf16 tile, pitch HP bf16
__device__ __forceinline__ void stage_tile(char* sdst, const __nv_bfloat16* src, int tid) {
#pragma unroll
    for (int it = 0; it < 16; it++) {
        int c = tid + it * 256;
        int row = c >> 5, ch = c & 31;
        uint4 v = *(const uint4*)(src + (size_t)row * DD + ch * 8);
        *(uint4*)(sdst + row * (HP * 2) + ch * 16) = v;
    }
}
__device__ __forceinline__ void stage_tile_cp(uint32_t sdst, const __nv_bfloat16* src, int tid) {
#pragma unroll
    for (int it = 0; it < 16; it++) {
        int c = tid + it * 256;
        int row = c >> 5, ch = c & 31;
        CP16(sdst + (uint32_t)(row * (HP * 2) + ch * 16),
             src + (size_t)row * DD + ch * 8);
    }
}

// ---------------- kernel 1: BN column stats ----------------------------------
__global__ void k_stats(const float* __restrict__ H,
                        const float* __restrict__ gamma,
                        const float* __restrict__ beta) {
    int c = threadIdx.x & 31, rr = threadIdx.x >> 5;
    int j = blockIdx.x * 32 + c;
    float s = 0.f, s2 = 0.f;
    for (int r = rr; r < NN; r += 8) {
        float x = H[(size_t)r * DD + j];
        s += x; s2 += x * x;
    }
    __shared__ float sh[8][32], sh2[8][32];
    sh[rr][c] = s; sh2[rr][c] = s2;
    __syncthreads();
    if (rr == 0) {
        float ts = 0.f, ts2 = 0.f;
#pragma unroll
        for (int q = 0; q < 8; q++) { ts += sh[q][c]; ts2 += sh2[q][c]; }
        float mu = ts * (1.f / NN);
        float var = ts2 * (1.f / NN) - mu * mu;
        float sc = gamma[j] * rsqrtf(var + 1e-5f);
        g_scale[j] = sc;
        g_shift[j] = beta[j] - mu * sc;
    }
}

// ---------------- kernel 2: BN + tiled transpose -> HnT ----------------------
__global__ void k_bnT(const float* __restrict__ H) {
    __shared__ float t[32][33];
    int x = blockIdx.x * 32 + threadIdx.x;
    int y = blockIdx.y * 32 + threadIdx.y;
    float sc = g_scale[x], sh = g_shift[x];
#pragma unroll
    for (int j = 0; j < 32; j += 8)
        t[threadIdx.y + j][threadIdx.x] = H[(size_t)(y + j) * DD + x] * sc + sh;
    __syncthreads();
    int x2 = blockIdx.y * 32 + threadIdx.x;
    int y2 = blockIdx.x * 32 + threadIdx.y;
#pragma unroll
    for (int j = 0; j < 32; j += 8)
        g_HnT[(size_t)(y2 + j) * NN + x2] = t[threadIdx.x][threadIdx.y + j];
}

// ---------------- SIMT GEMM micro-kernel -------------------------------------
__device__ __forceinline__ void mma_64x128(const float* __restrict__ sA,
                                           const float* __restrict__ sB,
                                           ull acc[4][4], int tx, int ty) {
#pragma unroll 8
    for (int k = 0; k < 256; k++) {
        float4 a4 = *(const float4*)(sA + k * PA + ty * 4);
        ulonglong2 b0 = *(const ulonglong2*)(sB + k * PB + tx * 4);
        ulonglong2 b1 = *(const ulonglong2*)(sB + k * PB + 64 + tx * 4);
        ull A0 = dup_f(a4.x), A1 = dup_f(a4.y), A2 = dup_f(a4.z), A3 = dup_f(a4.w);
        ffma2(acc[0][0], A0, b0.x); ffma2(acc[0][1], A0, b0.y);
        ffma2(acc[0][2], A0, b1.x); ffma2(acc[0][3], A0, b1.y);
        ffma2(acc[1][0], A1, b0.x); ffma2(acc[1][1], A1, b0.y);
        ffma2(acc[1][2], A1, b1.x); ffma2(acc[1][3], A1, b1.y);
        ffma2(acc[2][0], A2, b0.x); ffma2(acc[2][1], A2, b0.y);
        ffma2(acc[2][2], A2, b1.x); ffma2(acc[2][3], A2, b1.y);
        ffma2(acc[3][0], A3, b0.x); ffma2(acc[3][1], A3, b0.y);
        ffma2(acc[3][2], A3, b1.x); ffma2(acc[3][3], A3, b1.y);
    }
}

// ---------------- kernel 3: theta projection + row-normalize (fused) ---------
__global__ void __launch_bounds__(256, 1)
k_projT(const float* __restrict__ Wt, const float* __restrict__ bt) {
    extern __shared__ float sm[];
    float* sA = sm;
    float* sW = sm + 256 * PA;
    float* sq = sm + 256 * PA + 256 * PB;   // [64][17]
    float* srinv = sq + 64 * 17;            // [64]
    int tid = threadIdx.x, tx = tid & 15, ty = tid >> 4;
    int row0 = blockIdx.x * 64;

    for (int i = tid; i < 256 * 16; i += 256) {
        int mc = i & 15, k = i >> 4;
        *(float4*)(sA + k * PA + mc * 4) = *(const float4*)(g_HnT + (size_t)k * NN + row0 + mc * 4);
    }

    ull acc[2][4][4];
#pragma unroll
    for (int p = 0; p < 2; p++)
#pragma unroll
        for (int m = 0; m < 4; m++)
#pragma unroll
            for (int g = 0; g < 4; g++) acc[p][m][g] = 0ull;

    for (int p = 0; p < 2; p++) {
        __syncthreads();
        for (int i = tid; i < 256 * 32; i += 256) {
            int cc = i & 31, k = i >> 5;
            *(float4*)(sW + k * PB + cc * 4) = *(const float4*)(Wt + k * 256 + p * 128 + cc * 4);
        }
        __syncthreads();
        mma_64x128(sA, sW, acc[p], tx, ty);
    }

    // bias add + per-row sum of squares
    float vlo[2][4][4], vhi[2][4][4];
#pragma unroll
    for (int m = 0; m < 4; m++) {
        float ss = 0.f;
#pragma unroll
        for (int p = 0; p < 2; p++)
#pragma unroll
            for (int gj = 0; gj < 4; gj++) {
                int col = p * 128 + (gj >> 1) * 64 + tx * 4 + (gj & 1) * 2;
                float lo = lo32(acc[p][m][gj]) + bt[col];
                float hi = hi32(acc[p][m][gj]) + bt[col + 1];
                vlo[p][m][gj] = lo; vhi[p][m][gj] = hi;
                ss += lo * lo + hi * hi;
            }
        sq[(ty * 4 + m) * 17 + tx] = ss;
    }
    __syncthreads();
    if (tid < 64) {
        float s = 0.f;
#pragma unroll
        for (int q = 0; q < 16; q++) s += sq[tid * 17 + q];
        srinv[tid] = 1.0f / fmaxf(sqrtf(s), 1e-12f);
    }
    __syncthreads();
#pragma unroll
    for (int m = 0; m < 4; m++) {
        int row = row0 + ty * 4 + m;
        float ri = srinv[ty * 4 + m];
#pragma unroll
        for (int p = 0; p < 2; p++)
#pragma unroll
            for (int gj = 0; gj < 4; gj++) {
                int col = p * 128 + (gj >> 1) * 64 + tx * 4 + (gj & 1) * 2;
                float lo = vlo[p][m][gj] * ri;
                float hi = vhi[p][m][gj] * ri;
                *(float2*)(g_F1 + (size_t)row * DD + col) = make_float2(lo, hi);
                __nv_bfloat162 bb = __floats2bfloat162_rn(lo, hi);
                *(uint32_t*)(g_F1h + (size_t)row * DD + col) = *(uint32_t*)&bb;
            }
    }
}

// ---------------- kernel 4 (launch idx 3): HYBRID affinity screen ------------
#define TSW(q) if (tv[q] > tv[q-1]) { float _t = tv[q-1]; tv[q-1] = tv[q]; tv[q] = _t; \
                                      int _q = ti[q-1]; ti[q-1] = ti[q]; ti[q] = _q; }

__global__ void __launch_bounds__(256, 1) k_aff() {
    extern __shared__ char smc[];
    char* sAc = smc;
    char* sBc[2] = { smc + ABYTES, smc + 2 * ABYTES };
    uint32_t sbA = smem_u32(sAc);
    uint32_t sbB[2] = { smem_u32(sBc[0]), smem_u32(sBc[1]) };
    int tid = threadIdx.x, wid = tid >> 5, lane = tid & 31;
    int row0 = blockIdx.x * 128;
    int colbase0 = blockIdx.y * 4096;

    stage_tile(sAc, g_F1h + (size_t)row0 * DD, tid);
    stage_tile_cp(sbB[0], g_F1h + (size_t)colbase0 * DD, tid);
    CP_COMMIT();

    float tv[16];
    int ti[16];
#pragma unroll
    for (int q = 0; q < 16; q++) { tv[q] = -1e30f; ti[q] = 0; }

    // mma warps (0-3): rows wid*32..+31, cols 0-63
    uint32_t aBase = sbA + (uint32_t)(wid * 32 + (lane & 15)) * (HP * 2)
                   + (uint32_t)(lane >> 4) * 16;
    uint32_t bFragOff = (uint32_t)(((lane >> 4) << 3) + (lane & 7)) * (HP * 2)
                      + (uint32_t)((lane >> 3) & 1) * 16;
    // simt warps (4-7): rows (wid-4)*32 + tr + 4q, cols 64 + tc + 8p
    int sw = wid - 4, tr = lane & 3, tc = lane >> 2;
    uint32_t sAddrA = sbA + (uint32_t)(sw * 32 + tr) * (HP * 2);
    uint32_t sOffB = (uint32_t)(64 + tc) * (HP * 2);

    for (int t = 0; t < 32; t++) {
        int buf = t & 1;
        if (t + 1 < 32) {
            stage_tile_cp(sbB[buf ^ 1],
                          g_F1h + (size_t)(colbase0 + (t + 1) * 128) * DD, tid);
            CP_COMMIT();
            CP_WAIT(1);
        } else {
            CP_WAIT(0);
        }
        __syncthreads();

        float* sC = (float*)sBc[buf];

        if (wid < 4) {
            // ---- tensor-pipe half: cols 0-63 ----
            float acc[2][8][4];
#pragma unroll
            for (int mt = 0; mt < 2; mt++)
#pragma unroll
                for (int nt = 0; nt < 8; nt++)
#pragma unroll
                    for (int e = 0; e < 4; e++) acc[mt][nt][e] = 0.f;
            uint32_t bB = sbB[buf] + bFragOff;
#pragma unroll 1
            for (int ks = 0; ks < 16; ks++) {
                uint32_t a[2][4], b[4][4];
                ldmx4(a[0], aBase + ks * 32);
                ldmx4(a[1], aBase + 16 * (HP * 2) + ks * 32);
#pragma unroll
                for (int cg = 0; cg < 4; cg++)
                    ldmx4(b[cg], bB + (uint32_t)(cg * 16) * (HP * 2) + ks * 32);
#pragma unroll
                for (int mt = 0; mt < 2; mt++)
#pragma unroll
                    for (int nt = 0; nt < 8; nt++) {
                        int cg = nt >> 1, pr = nt & 1;
                        mma_bf16(acc[mt][nt], a[mt], b[cg][pr * 2], b[cg][pr * 2 + 1]);
                    }
            }
            __syncthreads();   // compute done; sB now reusable as C
#pragma unroll
            for (int mt = 0; mt < 2; mt++) {
                int rb = wid * 32 + mt * 16 + (lane >> 2);
#pragma unroll
                for (int nt = 0; nt < 8; nt++) {
                    int cb = nt * 8 + (lane & 3) * 2;
                    sC[cb * PCC + rb]           = acc[mt][nt][0];
                    sC[(cb + 1) * PCC + rb]     = acc[mt][nt][1];
                    sC[cb * PCC + rb + 8]       = acc[mt][nt][2];
                    sC[(cb + 1) * PCC + rb + 8] = acc[mt][nt][3];
                }
            }
        } else {
            // ---- fma-pipe half: cols 64-127, split-k packed accumulators ----
            ull acc[8][8];
#pragma unroll
            for (int q = 0; q < 8; q++)
#pragma unroll
                for (int p = 0; p < 8; p++) acc[q][p] = 0ull;
            uint32_t aA = sAddrA;
            uint32_t bA = sbB[buf] + sOffB;
            uint32_t aU[8], bU[8];
#pragma unroll
            for (int q = 0; q < 8; q++) aU[q] = lds32(aA + (uint32_t)(q * 4) * (HP * 2));
#pragma unroll
            for (int p = 0; p < 8; p++) bU[p] = lds32(bA + (uint32_t)(p * 8) * (HP * 2));
#pragma unroll 1
            for (int kp = 0; kp < 128; kp++) {
                ull aP[8], bP[8];
#pragma unroll
                for (int q = 0; q < 8; q++) aP[q] = cvt_bf2(aU[q]);
#pragma unroll
                for (int p = 0; p < 8; p++) bP[p] = cvt_bf2(bU[p]);
                if (kp + 1 < 128) {
                    uint32_t ka = aA + (kp + 1) * 4, kb = bA + (kp + 1) * 4;
#pragma unroll
                    for (int q = 0; q < 8; q++) aU[q] = lds32(ka + (uint32_t)(q * 4) * (HP * 2));
#pragma unroll
                    for (int p = 0; p < 8; p++) bU[p] = lds32(kb + (uint32_t)(p * 8) * (HP * 2));
                }
#pragma unroll
                for (int q = 0; q < 8; q++)
#pragma unroll
                    for (int p = 0; p < 8; p++) ffma2(acc[q][p], aP[q], bP[p]);
            }
            __syncthreads();   // matches mma warps' sync
#pragma unroll
            for (int q = 0; q < 8; q++) {
                int rb = sw * 32 + tr + 4 * q;
#pragma unroll
                for (int p = 0; p < 8; p++) {
                    int cb = 64 + tc + 8 * p;
                    sC[cb * PCC + rb] = __fadd_rn(lo32(acc[q][p]), hi32(acc[q][p]));
                }
            }
        }
        __syncthreads();

        if (tid < 128) {
            int colb = colbase0 + t * 128;
#pragma unroll 4
            for (int c = 0; c < 128; c++) {
                float v = sC[c * PCC + tid];
                if (v > tv[15]) {
                    tv[15] = v; ti[15] = colb + c;
                    TSW(15) TSW(14) TSW(13) TSW(12) TSW(11) TSW(10) TSW(9)
                    TSW(8) TSW(7) TSW(6) TSW(5) TSW(4) TSW(3) TSW(2) TSW(1)
                }
            }
        }
        __syncthreads();
    }
    if (tid < 128) {
        int r = row0 + tid;
#pragma unroll
        for (int q = 0; q < 16; q++)
            g_ci[(size_t)r * NC + blockIdx.y * 16 + q] = ti[q];
    }
}

// ---------------- kernel 5: W_out projection ---------------------------------
__global__ void __launch_bounds__(256, 1)
k_projO(const float* __restrict__ Wo, const float* __restrict__ bo) {
    extern __shared__ float sm[];
    float* sA = sm;
    float* sW = sm + 256 * PA;
    int tid = threadIdx.x, tx = tid & 15, ty = tid >> 4;
    int c0 = blockIdx.x * 128, row0 = blockIdx.y * 64;

    for (int i = tid; i < 256 * 16; i += 256) {
        int mc = i & 15, k = i >> 4;
        *(float4*)(sA + k * PA + mc * 4) = *(const float4*)(g_HnT + (size_t)k * NN + row0 + mc * 4);
    }
    for (int i = tid; i < 256 * 32; i += 256) {
        int cc = i & 31, k = i >> 5;
        *(float4*)(sW + k * PB + cc * 4) = *(const float4*)(Wo + k * 256 + c0 + cc * 4);
    }
    __syncthreads();

    ull acc[4][4];
#pragma unroll
    for (int m = 0; m < 4; m++)
#pragma unroll
        for (int p = 0; p < 4; p++) acc[m][p] = 0ull;
    mma_64x128(sA, sW, acc, tx, ty);

#pragma unroll
    for (int m = 0; m < 4; m++) {
        int r = row0 + ty * 4 + m;
#pragma unroll
        for (int g = 0; g < 2; g++) {
            int cg = c0 + g * 64 + tx * 4;
            float4 o;
            o.x = lo32(acc[m][2 * g + 0]) + bo[cg + 0];
            o.y = hi32(acc[m][2 * g + 0]) + bo[cg + 1];
            o.z = lo32(acc[m][2 * g + 1]) + bo[cg + 2];
            o.w = hi32(acc[m][2 * g + 1]) + bo[cg + 3];
            *(float4*)(g_B + (size_t)r * DD + cg) = o;
        }
    }
}

// ---------------- kernel 6: zero A region ------------------------------------
__global__ void k_zeroA(float* __restrict__ A) {
    size_t i = (size_t)blockIdx.x * blockDim.x + threadIdx.x;
    size_t total = (size_t)NN * NN / 4;
    float4 z = make_float4(0.f, 0.f, 0.f, 0.f);
    for (; i < total; i += (size_t)gridDim.x * blockDim.x) ((float4*)A)[i] = z;
}

// ---------------- A(d) ----------------
__device__ __forceinline__ float A32(float d) {
    d = fminf(fmaxf(d, -1.f), 1.f);
    float sam = acosf(d);
    float z = expf(-0.2f * sam);
    float s = 1.f / (1.f + expf(-z));
    return fmaxf(s, 0.1f);
}

// ---------------- kernel 7: rerank (compensated f32 exact dots) --------------
__global__ void __launch_bounds__(256) k_rerank(float* __restrict__ Aout) {
    int i = blockIdx.x;
    int t = threadIdx.x;
    int cand = t >> 3, chunk = t & 7;
    __shared__ float ssum[NC][8], scmp[NC][8];
    __shared__ int sci[NC];
    __shared__ float sdv[NC];
    if (t < NC) sci[t] = g_ci[(size_t)i * NC + t];
    __syncthreads();
    int j = sci[cand];
    const float* fi = g_F1 + (size_t)i * DD + chunk * 32;
    const float* fj = g_F1 + (size_t)j * DD + chunk * 32;
    float s = 0.f, comp = 0.f;
#pragma unroll
    for (int k = 0; k < 32; k += 4) {
        float4 a = *(const float4*)(fi + k);
        float4 b = *(const float4*)(fj + k);
        float av[4] = {a.x, a.y, a.z, a.w};
        float bv[4] = {b.x, b.y, b.z, b.w};
#pragma unroll
        for (int e = 0; e < 4; e++) {
            float p  = __fmul_rn(av[e], bv[e]);
            float e1 = __fmaf_rn(av[e], bv[e], -p);
            float tt = __fadd_rn(s, p);
            float bb = __fsub_rn(tt, s);
            float e2 = __fadd_rn(__fsub_rn(s, __fsub_rn(tt, bb)), __fsub_rn(p, bb));
            s = tt;
            comp = __fadd_rn(comp, __fadd_rn(e1, e2));
        }
    }
    ssum[cand][chunk] = s;
    scmp[cand][chunk] = comp;
    __syncthreads();
    if (t < NC) {
        float S = 0.f, C = 0.f;
#pragma unroll
        for (int c = 0; c < 8; c++) {
            float p  = ssum[t][c];
            float tt = __fadd_rn(S, p);
            float bb = __fsub_rn(tt, S);
            float e2 = __fadd_rn(__fsub_rn(S, __fsub_rn(tt, bb)), __fsub_rn(p, bb));
            S = tt;
            C = __fadd_rn(C, __fadd_rn(scmp[t][c], e2));
        }
        sdv[t] = __fadd_rn(S, C);
    }
    __syncthreads();
    if (t == 0) {
        float av[NC]; int ai[NC]; bool used[NC];
#pragma unroll
        for (int q = 0; q < NC; q++) {
            av[q] = A32(sdv[q]);
            ai[q] = sci[q];
            used[q] = false;
        }
        int oi[KTOP]; float oa[KTOP];
        for (int s5 = 0; s5 < KTOP; s5++) {
            int best = -1;
            for (int q = 0; q < NC; q++) {
                if (used[q]) continue;
                if (best < 0 || av[q] > av[best] ||
                    (av[q] == av[best] && ai[q] < ai[best])) best = q;
            }
            used[best] = true;
            oi[s5] = ai[best]; oa[s5] = av[best];
        }
        for (int a = 1; a < KTOP; a++) {
            int ky = oi[a]; float kv = oa[a]; int b = a - 1;
            while (b >= 0 && oi[b] > ky) { oi[b+1] = oi[b]; oa[b+1] = oa[b]; b--; }
            oi[b+1] = ky; oa[b+1] = kv;
        }
        float sum = 0.f;
#pragma unroll
        for (int s5 = 0; s5 < KTOP; s5++) {
            sum += oa[s5];
            g_topi[i * KTOP + s5] = oi[s5];
            g_av[i * KTOP + s5] = oa[s5];
            if (Aout) Aout[(size_t)i * NN + oi[s5]] = oa[s5];
        }
        g_dinv[i] = rsqrtf(sum);
    }
}

// ---------------- kernel 8: out ----------------------------------------------
__global__ void k_out(float* __restrict__ out) {
    int wid = threadIdx.x >> 5, lane = threadIdx.x & 31;
    int i = blockIdx.x * 8 + wid;
    float di = g_dinv[i];
    float a0[8] = {0.f, 0.f, 0.f, 0.f, 0.f, 0.f, 0.f, 0.f};
#pragma unroll
    for (int s = 0; s < KTOP; s++) {
        int j = g_topi[i * KTOP + s];
        float c = di * g_av[i * KTOP + s] * g_dinv[j];
        float4 b0 = *(const float4*)(g_B + (size_t)j * DD + lane * 4);
        float4 b1 = *(const float4*)(g_B + (size_t)j * DD + 128 + lane * 4);
        a0[0] = __fmaf_rn(c, b0.x, a0[0]); a0[1] = __fmaf_rn(c, b0.y, a0[1]);
        a0[2] = __fmaf_rn(c, b0.z, a0[2]); a0[3] = __fmaf_rn(c, b0.w, a0[3]);
        a0[4] = __fmaf_rn(c, b1.x, a0[4]); a0[5] = __fmaf_rn(c, b1.y, a0[5]);
        a0[6] = __fmaf_rn(c, b1.z, a0[6]); a0[7] = __fmaf_rn(c, b1.w, a0[7]);
    }
#pragma unroll
    for (int q = 0; q < 8; q++)
        a0[q] = (a0[q] >= 0.f) ? a0[q] : 0.01f * a0[q];
    *(float4*)(out + (size_t)i * DD + lane * 4) = make_float4(a0[0], a0[1], a0[2], a0[3]);
    *(float4*)(out + (size_t)i * DD + 128 + lane * 4) = make_float4(a0[4], a0[5], a0[6], a0[7]);
}

// ---------------- launch -----------------------------------------------------
extern "C" void kernel_launch(void* const* d_in, const int* in_sizes, int n_in,
                              void* d_out, int out_size) {
    const float* H     = (const float*)d_in[0];
    const float* gamma = (const float*)d_in[1];
    const float* beta  = (const float*)d_in[2];
    const float* Wt    = (const float*)d_in[3];
    const float* bt    = (const float*)d_in[4];
    const float* Wo    = (const float*)d_in[5];
    const float* bo    = (const float*)d_in[6];

    float* outp = (float*)d_out;
    float* Aout = ((size_t)out_size >= (size_t)NN * DD + (size_t)NN * NN)
                  ? outp + (size_t)NN * DD : nullptr;

    cudaFuncSetAttribute(k_projT, cudaFuncAttributeMaxDynamicSharedMemorySize, SMEMT_BYTES);
    cudaFuncSetAttribute(k_projO, cudaFuncAttributeMaxDynamicSharedMemorySize, SMEM_BYTES);
    cudaFuncSetAttribute(k_aff, cudaFuncAttributeMaxDynamicSharedMemorySize, AFF_SMEM);

    k_stats<<<DD / 32, 256>>>(H, gamma, beta);                    // 0
    { dim3 b(32, 8), g(DD / 32, NN / 32); k_bnT<<<g, b>>>(H); }   // 1
    k_projT<<<NN / 64, 256, SMEMT_BYTES>>>(Wt, bt);               // 2
    { dim3 g(NN / 128, 2); k_aff<<<g, 256, AFF_SMEM>>>(); }       // 3  <- ncu slot
    { dim3 g(2, NN / 64); k_projO<<<g, 256, SMEM_BYTES>>>(Wo, bo); } // 4
    if (Aout) k_zeroA<<<2048, 256>>>(Aout);                       // 5
    k_rerank<<<NN, 256>>>(Aout);                                  // 6
    k_out<<<NN / 8, 256>>>(outp);                                 // 7
}

// round 11
// speedup vs baseline: 2.0252x; 2.0252x over previous
#include <cuda_runtime.h>
#include <cuda_bf16.h>
#include <cstdint>
#include <math.h>

#define NN 8192
#define DD 256
#define KTOP 5
#define NC 32
#define PA 68
#define PB 132
#define SMEM_BYTES ((256 * PA + 256 * PB) * 4)
#define SMEMT_BYTES (SMEM_BYTES + (64 * 17 + 64) * 4)

#define HP 264                         // bf16 pitch (528B): conflict-free ldmatrix
#define ABYTES (128 * HP * 2)          // 67584 per tile buffer
#define AFF_SMEM (3 * ABYTES)          // A + B0 + B1 = 202752
#define PCC 129                        // C dump pitch (floats)
#define AFF_T 512

typedef unsigned long long ull;

// ---------------- scratch ----------------
__device__ float g_scale[DD];
__device__ float g_shift[DD];
__device__ float g_HnT[DD * NN];
__device__ float g_F1[NN * DD];
__device__ __nv_bfloat16 g_F1h[NN * DD];
__device__ float g_B[NN * DD];
__device__ int   g_ci[NN * NC];
__device__ int   g_topi[NN * KTOP];
__device__ float g_av[NN * KTOP];
__device__ float g_dinv[NN];

// ---------------- helpers ----------------
__device__ __forceinline__ ull dup_f(float a) {
    ull d; asm("mov.b64 %0, {%1, %1};" : "=l"(d) : "r"(__float_as_uint(a))); return d;
}
__device__ __forceinline__ void ffma2(ull& d, ull a, ull b) {
    asm("fma.rn.f32x2 %0, %1, %2, %0;" : "+l"(d) : "l"(a), "l"(b));
}
__device__ __forceinline__ float lo32(ull u) { return __uint_as_float((unsigned)u); }
__device__ __forceinline__ float hi32(ull u) { return __uint_as_float((unsigned)(u >> 32)); }

__device__ __forceinline__ uint32_t smem_u32(const void* p) {
    uint32_t a;
    asm("{ .reg .u64 t; cvta.to.shared.u64 t, %1; cvt.u32.u64 %0, t; }" : "=r"(a) : "l"(p));
    return a;
}
__device__ __forceinline__ void ldmx4(uint32_t* r, uint32_t addr) {
    asm volatile("ldmatrix.sync.aligned.m8n8.x4.shared.b16 {%0,%1,%2,%3}, [%4];"
        : "=r"(r[0]), "=r"(r[1]), "=r"(r[2]), "=r"(r[3]) : "r"(addr));
}
__device__ __forceinline__ void mma_bf16(float* d, const uint32_t* a,
                                         uint32_t b0, uint32_t b1) {
    asm volatile(
        "mma.sync.aligned.m16n8k16.row.col.f32.bf16.bf16.f32 "
        "{%0,%1,%2,%3}, {%4,%5,%6,%7}, {%8,%9}, {%0,%1,%2,%3};"
        : "+f"(d[0]), "+f"(d[1]), "+f"(d[2]), "+f"(d[3])
        : "r"(a[0]), "r"(a[1]), "r"(a[2]), "r"(a[3]), "r"(b0), "r"(b1));
}
#define CP16(dst, src) asm volatile("cp.async.ca.shared.global [%0], [%1], 16;" :: "r"(dst), "l"(src))
#define CP_COMMIT()    asm volatile("cp.async.commit_group;" ::: "memory")
#define CP_WAIT(n)     asm volatile("cp.async.wait_group %0;" :: "n"(n) : "memory")

// stage 128x256 bf16 tile, pitch HP bf16 (512-thread variants)
__device__ __forceinline__ void stage_tile(char* sdst, const __nv_bfloat16* src, int tid) {
#pragma unroll
    for (int it = 0; it < 8; it++) {
        int c = tid + it * AFF_T;
        int row = c >> 5, ch = c & 31;
        uint4 v = *(const uint4*)(src + (size_t)row * DD + ch * 8);
        *(uint4*)(sdst + row * (HP * 2) + ch * 16) = v;
    }
}
__device__ __forceinline__ void stage_tile_cp(uint32_t sdst, const __nv_bfloat16* src, int tid) {
#pragma unroll
    for (int it = 0; it < 8; it++) {
        int c = tid + it * AFF_T;
        int row = c >> 5, ch = c & 31;
        CP16(sdst + (uint32_t)(row * (HP * 2) + ch * 16),
             src + (size_t)row * DD + ch * 8);
    }
}

// ---------------- kernel 1: BN column stats ----------------------------------
__global__ void k_stats(const float* __restrict__ H,
                        const float* __restrict__ gamma,
                        const float* __restrict__ beta) {
    int c = threadIdx.x & 31, rr = threadIdx.x >> 5;
    int j = blockIdx.x * 32 + c;
    float s = 0.f, s2 = 0.f;
    for (int r = rr; r < NN; r += 8) {
        float x = H[(size_t)r * DD + j];
        s += x; s2 += x * x;
    }
    __shared__ float sh[8][32], sh2[8][32];
    sh[rr][c] = s; sh2[rr][c] = s2;
    __syncthreads();
    if (rr == 0) {
        float ts = 0.f, ts2 = 0.f;
#pragma unroll
        for (int q = 0; q < 8; q++) { ts += sh[q][c]; ts2 += sh2[q][c]; }
        float mu = ts * (1.f / NN);
        float var = ts2 * (1.f / NN) - mu * mu;
        float sc = gamma[j] * rsqrtf(var + 1e-5f);
        g_scale[j] = sc;
        g_shift[j] = beta[j] - mu * sc;
    }
}

// ---------------- kernel 2: BN + tiled transpose -> HnT ----------------------
__global__ void k_bnT(const float* __restrict__ H) {
    __shared__ float t[32][33];
    int x = blockIdx.x * 32 + threadIdx.x;
    int y = blockIdx.y * 32 + threadIdx.y;
    float sc = g_scale[x], sh = g_shift[x];
#pragma unroll
    for (int j = 0; j < 32; j += 8)
        t[threadIdx.y + j][threadIdx.x] = H[(size_t)(y + j) * DD + x] * sc + sh;
    __syncthreads();
    int x2 = blockIdx.y * 32 + threadIdx.x;
    int y2 = blockIdx.x * 32 + threadIdx.y;
#pragma unroll
    for (int j = 0; j < 32; j += 8)
        g_HnT[(size_t)(y2 + j) * NN + x2] = t[threadIdx.x][threadIdx.y + j];
}

// ---------------- SIMT GEMM micro-kernel -------------------------------------
__device__ __forceinline__ void mma_64x128(const float* __restrict__ sA,
                                           const float* __restrict__ sB,
                                           ull acc[4][4], int tx, int ty) {
#pragma unroll 8
    for (int k = 0; k < 256; k++) {
        float4 a4 = *(const float4*)(sA + k * PA + ty * 4);
        ulonglong2 b0 = *(const ulonglong2*)(sB + k * PB + tx * 4);
        ulonglong2 b1 = *(const ulonglong2*)(sB + k * PB + 64 + tx * 4);
        ull A0 = dup_f(a4.x), A1 = dup_f(a4.y), A2 = dup_f(a4.z), A3 = dup_f(a4.w);
        ffma2(acc[0][0], A0, b0.x); ffma2(acc[0][1], A0, b0.y);
        ffma2(acc[0][2], A0, b1.x); ffma2(acc[0][3], A0, b1.y);
        ffma2(acc[1][0], A1, b0.x); ffma2(acc[1][1], A1, b0.y);
        ffma2(acc[1][2], A1, b1.x); ffma2(acc[1][3], A1, b1.y);
        ffma2(acc[2][0], A2, b0.x); ffma2(acc[2][1], A2, b0.y);
        ffma2(acc[2][2], A2, b1.x); ffma2(acc[2][3], A2, b1.y);
        ffma2(acc[3][0], A3, b0.x); ffma2(acc[3][1], A3, b0.y);
        ffma2(acc[3][2], A3, b1.x); ffma2(acc[3][3], A3, b1.y);
    }
}

// ---------------- kernel 3: theta projection + row-normalize (fused) ---------
__global__ void __launch_bounds__(256, 1)
k_projT(const float* __restrict__ Wt, const float* __restrict__ bt) {
    extern __shared__ float sm[];
    float* sA = sm;
    float* sW = sm + 256 * PA;
    float* sq = sm + 256 * PA + 256 * PB;   // [64][17]
    float* srinv = sq + 64 * 17;            // [64]
    int tid = threadIdx.x, tx = tid & 15, ty = tid >> 4;
    int row0 = blockIdx.x * 64;

    for (int i = tid; i < 256 * 16; i += 256) {
        int mc = i & 15, k = i >> 4;
        *(float4*)(sA + k * PA + mc * 4) = *(const float4*)(g_HnT + (size_t)k * NN + row0 + mc * 4);
    }

    ull acc[2][4][4];
#pragma unroll
    for (int p = 0; p < 2; p++)
#pragma unroll
        for (int m = 0; m < 4; m++)
#pragma unroll
            for (int g = 0; g < 4; g++) acc[p][m][g] = 0ull;

    for (int p = 0; p < 2; p++) {
        __syncthreads();
        for (int i = tid; i < 256 * 32; i += 256) {
            int cc = i & 31, k = i >> 5;
            *(float4*)(sW + k * PB + cc * 4) = *(const float4*)(Wt + k * 256 + p * 128 + cc * 4);
        }
        __syncthreads();
        mma_64x128(sA, sW, acc[p], tx, ty);
    }

    float vlo[2][4][4], vhi[2][4][4];
#pragma unroll
    for (int m = 0; m < 4; m++) {
        float ss = 0.f;
#pragma unroll
        for (int p = 0; p < 2; p++)
#pragma unroll
            for (int gj = 0; gj < 4; gj++) {
                int col = p * 128 + (gj >> 1) * 64 + tx * 4 + (gj & 1) * 2;
                float lo = lo32(acc[p][m][gj]) + bt[col];
                float hi = hi32(acc[p][m][gj]) + bt[col + 1];
                vlo[p][m][gj] = lo; vhi[p][m][gj] = hi;
                ss += lo * lo + hi * hi;
            }
        sq[(ty * 4 + m) * 17 + tx] = ss;
    }
    __syncthreads();
    if (tid < 64) {
        float s = 0.f;
#pragma unroll
        for (int q = 0; q < 16; q++) s += sq[tid * 17 + q];
        srinv[tid] = 1.0f / fmaxf(sqrtf(s), 1e-12f);
    }
    __syncthreads();
#pragma unroll
    for (int m = 0; m < 4; m++) {
        int row = row0 + ty * 4 + m;
        float ri = srinv[ty * 4 + m];
#pragma unroll
        for (int p = 0; p < 2; p++)
#pragma unroll
            for (int gj = 0; gj < 4; gj++) {
                int col = p * 128 + (gj >> 1) * 64 + tx * 4 + (gj & 1) * 2;
                float lo = vlo[p][m][gj] * ri;
                float hi = vhi[p][m][gj] * ri;
                *(float2*)(g_F1 + (size_t)row * DD + col) = make_float2(lo, hi);
                __nv_bfloat162 bb = __floats2bfloat162_rn(lo, hi);
                *(uint32_t*)(g_F1h + (size_t)row * DD + col) = *(uint32_t*)&bb;
            }
    }
}

// ---------------- kernel 4 (launch idx 3): pure-mma screen, 16 warps ---------
#define TS8(q) if (tv[q] > tv[q-1]) { float _t = tv[q-1]; tv[q-1] = tv[q]; tv[q] = _t; \
                                      int _q = ti[q-1]; ti[q-1] = ti[q]; ti[q] = _q; }

__global__ void __launch_bounds__(AFF_T, 1) k_aff() {
    extern __shared__ char smc[];
    char* sAc = smc;
    char* sBc[2] = { smc + ABYTES, smc + 2 * ABYTES };
    uint32_t sbA = smem_u32(sAc);
    uint32_t sbB[2] = { smem_u32(sBc[0]), smem_u32(sBc[1]) };
    int tid = threadIdx.x, wid = tid >> 5, lane = tid & 31;
    int warp_m = wid & 3, warp_n = wid >> 2;       // 4 x 4 warp grid, 32x32 tiles
    int row0 = blockIdx.x * 128;
    int colbase0 = blockIdx.y * 4096;

    stage_tile(sAc, g_F1h + (size_t)row0 * DD, tid);
    stage_tile_cp(sbB[0], g_F1h + (size_t)colbase0 * DD, tid);
    CP_COMMIT();

    float tv[8];
    int ti[8];
#pragma unroll
    for (int q = 0; q < 8; q++) { tv[q] = -1e30f; ti[q] = 0; }

    uint32_t aBase = sbA + (uint32_t)(warp_m * 32 + (lane & 15)) * (HP * 2)
                   + (uint32_t)(lane >> 4) * 16;
    uint32_t bFragOff = (uint32_t)(warp_n * 32 + ((lane >> 4) << 3) + (lane & 7)) * (HP * 2)
                      + (uint32_t)((lane >> 3) & 1) * 16;
    int srow = tid & 127, shalf = (tid >> 7) & 1;   // scan mapping (threads 0-255)

    for (int t = 0; t < 32; t++) {
        int buf = t & 1;
        if (t + 1 < 32) {
            stage_tile_cp(sbB[buf ^ 1],
                          g_F1h + (size_t)(colbase0 + (t + 1) * 128) * DD, tid);
            CP_COMMIT();
            CP_WAIT(1);
        } else {
            CP_WAIT(0);
        }
        __syncthreads();

        float acc[2][4][4];
#pragma unroll
        for (int mt = 0; mt < 2; mt++)
#pragma unroll
            for (int g = 0; g < 4; g++)
#pragma unroll
                for (int e = 0; e < 4; e++) acc[mt][g][e] = 0.f;

        uint32_t bB = sbB[buf] + bFragOff;
#pragma unroll 1
        for (int ks = 0; ks < 16; ks++) {
            uint32_t a[2][4], b[2][4];
            ldmx4(a[0], aBase + ks * 32);
            ldmx4(a[1], aBase + 16 * (HP * 2) + ks * 32);
            ldmx4(b[0], bB + ks * 32);
            ldmx4(b[1], bB + 16 * (HP * 2) + ks * 32);
#pragma unroll
            for (int mt = 0; mt < 2; mt++)
#pragma unroll
                for (int nf = 0; nf < 2; nf++) {
                    mma_bf16(acc[mt][nf * 2 + 0], a[mt], b[nf][0], b[nf][1]);
                    mma_bf16(acc[mt][nf * 2 + 1], a[mt], b[nf][2], b[nf][3]);
                }
        }
        __syncthreads();     // compute done; sB[buf] reusable as C

        float* sC = (float*)sBc[buf];
#pragma unroll
        for (int mt = 0; mt < 2; mt++) {
            int rb = warp_m * 32 + mt * 16 + (lane >> 2);
#pragma unroll
            for (int g = 0; g < 4; g++) {
                int cb = warp_n * 32 + (g >> 1) * 16 + (g & 1) * 8 + (lane & 3) * 2;
                sC[cb * PCC + rb]           = acc[mt][g][0];
                sC[(cb + 1) * PCC + rb]     = acc[mt][g][1];
                sC[cb * PCC + rb + 8]       = acc[mt][g][2];
                sC[(cb + 1) * PCC + rb + 8] = acc[mt][g][3];
            }
        }
        __syncthreads();

        if (tid < 256) {
            int colb = colbase0 + t * 128 + shalf * 64;
            const float* base = sC + (shalf * 64) * PCC + srow;
#pragma unroll 4
            for (int c = 0; c < 64; c++) {
                float v = base[c * PCC];
                if (v > tv[7]) {
                    tv[7] = v; ti[7] = colb + c;
                    TS8(7) TS8(6) TS8(5) TS8(4) TS8(3) TS8(2) TS8(1)
                }
            }
        }
        __syncthreads();
    }
    if (tid < 256) {
        int r = row0 + srow;
        int base = blockIdx.y * 16 + shalf * 8;
#pragma unroll
        for (int q = 0; q < 8; q++)
            g_ci[(size_t)r * NC + base + q] = ti[q];
    }
}

// ---------------- kernel 5: W_out projection ---------------------------------
__global__ void __launch_bounds__(256, 1)
k_projO(const float* __restrict__ Wo, const float* __restrict__ bo) {
    extern __shared__ float sm[];
    float* sA = sm;
    float* sW = sm + 256 * PA;
    int tid = threadIdx.x, tx = tid & 15, ty = tid >> 4;
    int c0 = blockIdx.x * 128, row0 = blockIdx.y * 64;

    for (int i = tid; i < 256 * 16; i += 256) {
        int mc = i & 15, k = i >> 4;
        *(float4*)(sA + k * PA + mc * 4) = *(const float4*)(g_HnT + (size_t)k * NN + row0 + mc * 4);
    }
    for (int i = tid; i < 256 * 32; i += 256) {
        int cc = i & 31, k = i >> 5;
        *(float4*)(sW + k * PB + cc * 4) = *(const float4*)(Wo + k * 256 + c0 + cc * 4);
    }
    __syncthreads();

    ull acc[4][4];
#pragma unroll
    for (int m = 0; m < 4; m++)
#pragma unroll
        for (int p = 0; p < 4; p++) acc[m][p] = 0ull;
    mma_64x128(sA, sW, acc, tx, ty);

#pragma unroll
    for (int m = 0; m < 4; m++) {
        int r = row0 + ty * 4 + m;
#pragma unroll
        for (int g = 0; g < 2; g++) {
            int cg = c0 + g * 64 + tx * 4;
            float4 o;
            o.x = lo32(acc[m][2 * g + 0]) + bo[cg + 0];
            o.y = hi32(acc[m][2 * g + 0]) + bo[cg + 1];
            o.z = lo32(acc[m][2 * g + 1]) + bo[cg + 2];
            o.w = hi32(acc[m][2 * g + 1]) + bo[cg + 3];
            *(float4*)(g_B + (size_t)r * DD + cg) = o;
        }
    }
}

// ---------------- kernel 6: zero A region ------------------------------------
__global__ void k_zeroA(float* __restrict__ A) {
    size_t i = (size_t)blockIdx.x * blockDim.x + threadIdx.x;
    size_t total = (size_t)NN * NN / 4;
    float4 z = make_float4(0.f, 0.f, 0.f, 0.f);
    for (; i < total; i += (size_t)gridDim.x * blockDim.x) ((float4*)A)[i] = z;
}

// ---------------- A(d) ----------------
__device__ __forceinline__ float A32(float d) {
    d = fminf(fmaxf(d, -1.f), 1.f);
    float sam = acosf(d);
    float z = expf(-0.2f * sam);
    float s = 1.f / (1.f + expf(-z));
    return fmaxf(s, 0.1f);
}

// ---------------- kernel 7: rerank (compensated f32 exact dots) --------------
__global__ void __launch_bounds__(256) k_rerank(float* __restrict__ Aout) {
    int i = blockIdx.x;
    int t = threadIdx.x;
    int cand = t >> 3, chunk = t & 7;
    __shared__ float ssum[NC][8], scmp[NC][8];
    __shared__ int sci[NC];
    __shared__ float sdv[NC];
    if (t < NC) sci[t] = g_ci[(size_t)i * NC + t];
    __syncthreads();
    int j = sci[cand];
    const float* fi = g_F1 + (size_t)i * DD + chunk * 32;
    const float* fj = g_F1 + (size_t)j * DD + chunk * 32;
    float s = 0.f, comp = 0.f;
#pragma unroll
    for (int k = 0; k < 32; k += 4) {
        float4 a = *(const float4*)(fi + k);
        float4 b = *(const float4*)(fj + k);
        float av[4] = {a.x, a.y, a.z, a.w};
        float bv[4] = {b.x, b.y, b.z, b.w};
#pragma unroll
        for (int e = 0; e < 4; e++) {
            float p  = __fmul_rn(av[e], bv[e]);
            float e1 = __fmaf_rn(av[e], bv[e], -p);
            float tt = __fadd_rn(s, p);
            float bb = __fsub_rn(tt, s);
            float e2 = __fadd_rn(__fsub_rn(s, __fsub_rn(tt, bb)), __fsub_rn(p, bb));
            s = tt;
            comp = __fadd_rn(comp, __fadd_rn(e1, e2));
        }
    }
    ssum[cand][chunk] = s;
    scmp[cand][chunk] = comp;
    __syncthreads();
    if (t < NC) {
        float S = 0.f, C = 0.f;
#pragma unroll
        for (int c = 0; c < 8; c++) {
            float p  = ssum[t][c];
            float tt = __fadd_rn(S, p);
            float bb = __fsub_rn(tt, S);
            float e2 = __fadd_rn(__fsub_rn(S, __fsub_rn(tt, bb)), __fsub_rn(p, bb));
            S = tt;
            C = __fadd_rn(C, __fadd_rn(scmp[t][c], e2));
        }
        sdv[t] = __fadd_rn(S, C);
    }
    __syncthreads();
    if (t == 0) {
        float av[NC]; int ai[NC]; bool used[NC];
#pragma unroll
        for (int q = 0; q < NC; q++) {
            av[q] = A32(sdv[q]);
            ai[q] = sci[q];
            used[q] = false;
        }
        int oi[KTOP]; float oa[KTOP];
        for (int s5 = 0; s5 < KTOP; s5++) {
            int best = -1;
            for (int q = 0; q < NC; q++) {
                if (used[q]) continue;
                if (best < 0 || av[q] > av[best] ||
                    (av[q] == av[best] && ai[q] < ai[best])) best = q;
            }
            used[best] = true;
            oi[s5] = ai[best]; oa[s5] = av[best];
        }
        for (int a = 1; a < KTOP; a++) {
            int ky = oi[a]; float kv = oa[a]; int b = a - 1;
            while (b >= 0 && oi[b] > ky) { oi[b+1] = oi[b]; oa[b+1] = oa[b]; b--; }
            oi[b+1] = ky; oa[b+1] = kv;
        }
        float sum = 0.f;
#pragma unroll
        for (int s5 = 0; s5 < KTOP; s5++) {
            sum += oa[s5];
            g_topi[i * KTOP + s5] = oi[s5];
            g_av[i * KTOP + s5] = oa[s5];
            if (Aout) Aout[(size_t)i * NN + oi[s5]] = oa[s5];
        }
        g_dinv[i] = rsqrtf(sum);
    }
}

// ---------------- kernel 8: out ----------------------------------------------
__global__ void k_out(float* __restrict__ out) {
    int wid = threadIdx.x >> 5, lane = threadIdx.x & 31;
    int i = blockIdx.x * 8 + wid;
    float di = g_dinv[i];
    float a0[8] = {0.f, 0.f, 0.f, 0.f, 0.f, 0.f, 0.f, 0.f};
#pragma unroll
    for (int s = 0; s < KTOP; s++) {
        int j = g_topi[i * KTOP + s];
        float c = di * g_av[i * KTOP + s] * g_dinv[j];
        float4 b0 = *(const float4*)(g_B + (size_t)j * DD + lane * 4);
        float4 b1 = *(const float4*)(g_B + (size_t)j * DD + 128 + lane * 4);
        a0[0] = __fmaf_rn(c, b0.x, a0[0]); a0[1] = __fmaf_rn(c, b0.y, a0[1]);
        a0[2] = __fmaf_rn(c, b0.z, a0[2]); a0[3] = __fmaf_rn(c, b0.w, a0[3]);
        a0[4] = __fmaf_rn(c, b1.x, a0[4]); a0[5] = __fmaf_rn(c, b1.y, a0[5]);
        a0[6] = __fmaf_rn(c, b1.z, a0[6]); a0[7] = __fmaf_rn(c, b1.w, a0[7]);
    }
#pragma unroll
    for (int q = 0; q < 8; q++)
        a0[q] = (a0[q] >= 0.f) ? a0[q] : 0.01f * a0[q];
    *(float4*)(out + (size_t)i * DD + lane * 4) = make_float4(a0[0], a0[1], a0[2], a0[3]);
    *(float4*)(out + (size_t)i * DD + 128 + lane * 4) = make_float4(a0[4], a0[5], a0[6], a0[7]);
}

// ---------------- launch -----------------------------------------------------
extern "C" void kernel_launch(void* const* d_in, const int* in_sizes, int n_in,
                              void* d_out, int out_size) {
    const float* H     = (const float*)d_in[0];
    const float* gamma = (const float*)d_in[1];
    const float* beta  = (const float*)d_in[2];
    const float* Wt    = (const float*)d_in[3];
    const float* bt    = (const float*)d_in[4];
    const float* Wo    = (const float*)d_in[5];
    const float* bo    = (const float*)d_in[6];

    float* outp = (float*)d_out;
    float* Aout = ((size_t)out_size >= (size_t)NN * DD + (size_t)NN * NN)
                  ? outp + (size_t)NN * DD : nullptr;

    cudaFuncSetAttribute(k_projT, cudaFuncAttributeMaxDynamicSharedMemorySize, SMEMT_BYTES);
    cudaFuncSetAttribute(k_projO, cudaFuncAttributeMaxDynamicSharedMemorySize, SMEM_BYTES);
    cudaFuncSetAttribute(k_aff, cudaFuncAttributeMaxDynamicSharedMemorySize, AFF_SMEM);

    k_stats<<<DD / 32, 256>>>(H, gamma, beta);                       // 0
    { dim3 b(32, 8), g(DD / 32, NN / 32); k_bnT<<<g, b>>>(H); }      // 1
    k_projT<<<NN / 64, 256, SMEMT_BYTES>>>(Wt, bt);                  // 2
    { dim3 g(NN / 128, 2); k_aff<<<g, AFF_T, AFF_SMEM>>>(); }        // 3  <- ncu slot
    { dim3 g(2, NN / 64); k_projO<<<g, 256, SMEM_BYTES>>>(Wo, bo); } // 4
    if (Aout) k_zeroA<<<2048, 256>>>(Aout);                          // 5
    k_rerank<<<NN, 256>>>(Aout);                                     // 6
    k_out<<<NN / 8, 256>>>(outp);                                    // 7
}

// round 13
// speedup vs baseline: 2.4885x; 1.2288x over previous
#include <cuda_runtime.h>
#include <cuda_bf16.h>
#include <cstdint>
#include <math.h>

#define NN 8192
#define DD 256
#define KTOP 5
#define NC 32
#define PA 68
#define PB 132
#define SMEM_BYTES ((256 * PA + 256 * PB) * 4)
#define SMEMT_BYTES (SMEM_BYTES + (64 * 17 + 64) * 4)

#define HP 264                         // bf16 pitch (528B): conflict-free ldmatrix
#define ABYTES (128 * HP * 2)          // 67584 per tile buffer
#define AFF_SMEM (3 * ABYTES)          // A + B0 + B1 = 202752
#define PCC 129                        // C dump pitch (floats)
#define AFF_T 512

typedef unsigned long long ull;

// ---------------- scratch ----------------
__device__ float g_scale[DD];
__device__ float g_shift[DD];
__device__ float g_HnT[DD * NN];
__device__ float g_F1[NN * DD];
__device__ __nv_bfloat16 g_F1h[NN * DD];
__device__ float g_B[NN * DD];
__device__ int   g_ci[NN * NC];
__device__ int   g_topi[NN * KTOP];
__device__ float g_av[NN * KTOP];
__device__ float g_dinv[NN];

// ---------------- helpers ----------------
__device__ __forceinline__ ull dup_f(float a) {
    ull d; asm("mov.b64 %0, {%1, %1};" : "=l"(d) : "r"(__float_as_uint(a))); return d;
}
__device__ __forceinline__ void ffma2(ull& d, ull a, ull b) {
    asm("fma.rn.f32x2 %0, %1, %2, %0;" : "+l"(d) : "l"(a), "l"(b));
}
__device__ __forceinline__ float lo32(ull u) { return __uint_as_float((unsigned)u); }
__device__ __forceinline__ float hi32(ull u) { return __uint_as_float((unsigned)(u >> 32)); }

__device__ __forceinline__ uint32_t smem_u32(const void* p) {
    uint32_t a;
    asm("{ .reg .u64 t; cvta.to.shared.u64 t, %1; cvt.u32.u64 %0, t; }" : "=r"(a) : "l"(p));
    return a;
}
__device__ __forceinline__ void ldmx4(uint32_t* r, uint32_t addr) {
    asm volatile("ldmatrix.sync.aligned.m8n8.x4.shared.b16 {%0,%1,%2,%3}, [%4];"
        : "=r"(r[0]), "=r"(r[1]), "=r"(r[2]), "=r"(r[3]) : "r"(addr));
}
__device__ __forceinline__ void mma_bf16(float* d, const uint32_t* a,
                                         uint32_t b0, uint32_t b1) {
    asm volatile(
        "mma.sync.aligned.m16n8k16.row.col.f32.bf16.bf16.f32 "
        "{%0,%1,%2,%3}, {%4,%5,%6,%7}, {%8,%9}, {%0,%1,%2,%3};"
        : "+f"(d[0]), "+f"(d[1]), "+f"(d[2]), "+f"(d[3])
        : "r"(a[0]), "r"(a[1]), "r"(a[2]), "r"(a[3]), "r"(b0), "r"(b1));
}
#define CP16(dst, src) asm volatile("cp.async.ca.shared.global [%0], [%1], 16;" :: "r"(dst), "l"(src))
#define CP_COMMIT()    asm volatile("cp.async.commit_group;" ::: "memory")
#define CP_WAIT(n)     asm volatile("cp.async.wait_group %0;" :: "n"(n) : "memory")

// stage 128x256 bf16 tile, pitch HP bf16 (512-thread variants)
__device__ __forceinline__ void stage_tile(char* sdst, const __nv_bfloat16* src, int tid) {
#pragma unroll
    for (int it = 0; it < 8; it++) {
        int c = tid + it * AFF_T;
        int row = c >> 5, ch = c & 31;
        uint4 v = *(const uint4*)(src + (size_t)row * DD + ch * 8);
        *(uint4*)(sdst + row * (HP * 2) + ch * 16) = v;
    }
}
__device__ __forceinline__ void stage_tile_cp(uint32_t sdst, const __nv_bfloat16* src, int tid) {
#pragma unroll
    for (int it = 0; it < 8; it++) {
        int c = tid + it * AFF_T;
        int row = c >> 5, ch = c & 31;
        CP16(sdst + (uint32_t)(row * (HP * 2) + ch * 16),
             src + (size_t)row * DD + ch * 8);
    }
}

// ---------------- kernel 1: BN column stats ----------------------------------
__global__ void k_stats(const float* __restrict__ H,
                        const float* __restrict__ gamma,
                        const float* __restrict__ beta) {
    int c = threadIdx.x & 31, rr = threadIdx.x >> 5;
    int j = blockIdx.x * 32 + c;
    float s = 0.f, s2 = 0.f;
    for (int r = rr; r < NN; r += 8) {
        float x = H[(size_t)r * DD + j];
        s += x; s2 += x * x;
    }
    __shared__ float sh[8][32], sh2[8][32];
    sh[rr][c] = s; sh2[rr][c] = s2;
    __syncthreads();
    if (rr == 0) {
        float ts = 0.f, ts2 = 0.f;
#pragma unroll
        for (int q = 0; q < 8; q++) { ts += sh[q][c]; ts2 += sh2[q][c]; }
        float mu = ts * (1.f / NN);
        float var = ts2 * (1.f / NN) - mu * mu;
        float sc = gamma[j] * rsqrtf(var + 1e-5f);
        g_scale[j] = sc;
        g_shift[j] = beta[j] - mu * sc;
    }
}

// ---------------- kernel 2: BN + tiled transpose -> HnT ----------------------
__global__ void k_bnT(const float* __restrict__ H) {
    __shared__ float t[32][33];
    int x = blockIdx.x * 32 + threadIdx.x;
    int y = blockIdx.y * 32 + threadIdx.y;
    float sc = g_scale[x], sh = g_shift[x];
#pragma unroll
    for (int j = 0; j < 32; j += 8)
        t[threadIdx.y + j][threadIdx.x] = H[(size_t)(y + j) * DD + x] * sc + sh;
    __syncthreads();
    int x2 = blockIdx.y * 32 + threadIdx.x;
    int y2 = blockIdx.x * 32 + threadIdx.y;
#pragma unroll
    for (int j = 0; j < 32; j += 8)
        g_HnT[(size_t)(y2 + j) * NN + x2] = t[threadIdx.x][threadIdx.y + j];
}

// ---------------- SIMT GEMM micro-kernel -------------------------------------
__device__ __forceinline__ void mma_64x128(const float* __restrict__ sA,
                                           const float* __restrict__ sB,
                                           ull acc[4][4], int tx, int ty) {
#pragma unroll 8
    for (int k = 0; k < 256; k++) {
        float4 a4 = *(const float4*)(sA + k * PA + ty * 4);
        ulonglong2 b0 = *(const ulonglong2*)(sB + k * PB + tx * 4);
        ulonglong2 b1 = *(const ulonglong2*)(sB + k * PB + 64 + tx * 4);
        ull A0 = dup_f(a4.x), A1 = dup_f(a4.y), A2 = dup_f(a4.z), A3 = dup_f(a4.w);
        ffma2(acc[0][0], A0, b0.x); ffma2(acc[0][1], A0, b0.y);
        ffma2(acc[0][2], A0, b1.x); ffma2(acc[0][3], A0, b1.y);
        ffma2(acc[1][0], A1, b0.x); ffma2(acc[1][1], A1, b0.y);
        ffma2(acc[1][2], A1, b1.x); ffma2(acc[1][3], A1, b1.y);
        ffma2(acc[2][0], A2, b0.x); ffma2(acc[2][1], A2, b0.y);
        ffma2(acc[2][2], A2, b1.x); ffma2(acc[2][3], A2, b1.y);
        ffma2(acc[3][0], A3, b0.x); ffma2(acc[3][1], A3, b0.y);
        ffma2(acc[3][2], A3, b1.x); ffma2(acc[3][3], A3, b1.y);
    }
}

// ---------------- kernel 3: theta projection + row-normalize (fused) ---------
__global__ void __launch_bounds__(256, 1)
k_projT(const float* __restrict__ Wt, const float* __restrict__ bt) {
    extern __shared__ float sm[];
    float* sA = sm;
    float* sW = sm + 256 * PA;
    float* sq = sm + 256 * PA + 256 * PB;   // [64][17]
    float* srinv = sq + 64 * 17;            // [64]
    int tid = threadIdx.x, tx = tid & 15, ty = tid >> 4;
    int row0 = blockIdx.x * 64;

    for (int i = tid; i < 256 * 16; i += 256) {
        int mc = i & 15, k = i >> 4;
        *(float4*)(sA + k * PA + mc * 4) = *(const float4*)(g_HnT + (size_t)k * NN + row0 + mc * 4);
    }

    ull acc[2][4][4];
#pragma unroll
    for (int p = 0; p < 2; p++)
#pragma unroll
        for (int m = 0; m < 4; m++)
#pragma unroll
            for (int g = 0; g < 4; g++) acc[p][m][g] = 0ull;

    for (int p = 0; p < 2; p++) {
        __syncthreads();
        for (int i = tid; i < 256 * 32; i += 256) {
            int cc = i & 31, k = i >> 5;
            *(float4*)(sW + k * PB + cc * 4) = *(const float4*)(Wt + k * 256 + p * 128 + cc * 4);
        }
        __syncthreads();
        mma_64x128(sA, sW, acc[p], tx, ty);
    }

    float vlo[2][4][4], vhi[2][4][4];
#pragma unroll
    for (int m = 0; m < 4; m++) {
        float ss = 0.f;
#pragma unroll
        for (int p = 0; p < 2; p++)
#pragma unroll
            for (int gj = 0; gj < 4; gj++) {
                int col = p * 128 + (gj >> 1) * 64 + tx * 4 + (gj & 1) * 2;
                float lo = lo32(acc[p][m][gj]) + bt[col];
                float hi = hi32(acc[p][m][gj]) + bt[col + 1];
                vlo[p][m][gj] = lo; vhi[p][m][gj] = hi;
                ss += lo * lo + hi * hi;
            }
        sq[(ty * 4 + m) * 17 + tx] = ss;
    }
    __syncthreads();
    if (tid < 64) {
        float s = 0.f;
#pragma unroll
        for (int q = 0; q < 16; q++) s += sq[tid * 17 + q];
        srinv[tid] = 1.0f / fmaxf(sqrtf(s), 1e-12f);
    }
    __syncthreads();
#pragma unroll
    for (int m = 0; m < 4; m++) {
        int row = row0 + ty * 4 + m;
        float ri = srinv[ty * 4 + m];
#pragma unroll
        for (int p = 0; p < 2; p++)
#pragma unroll
            for (int gj = 0; gj < 4; gj++) {
                int col = p * 128 + (gj >> 1) * 64 + tx * 4 + (gj & 1) * 2;
                float lo = vlo[p][m][gj] * ri;
                float hi = vhi[p][m][gj] * ri;
                *(float2*)(g_F1 + (size_t)row * DD + col) = make_float2(lo, hi);
                __nv_bfloat162 bb = __floats2bfloat162_rn(lo, hi);
                *(uint32_t*)(g_F1h + (size_t)row * DD + col) = *(uint32_t*)&bb;
            }
    }
}

// ---------------- kernel 4 (launch idx 3): pure-mma screen, 16 warps ---------
#define TS8(q) if (tv[q] > tv[q-1]) { float _t = tv[q-1]; tv[q-1] = tv[q]; tv[q] = _t; \
                                      int _q = ti[q-1]; ti[q-1] = ti[q]; ti[q] = _q; }

__global__ void __launch_bounds__(AFF_T, 1) k_aff() {
    extern __shared__ char smc[];
    char* sAc = smc;
    char* sBc[2] = { smc + ABYTES, smc + 2 * ABYTES };
    uint32_t sbA = smem_u32(sAc);
    uint32_t sbB[2] = { smem_u32(sBc[0]), smem_u32(sBc[1]) };
    int tid = threadIdx.x, wid = tid >> 5, lane = tid & 31;
    int warp_m = wid & 3, warp_n = wid >> 2;       // 4 x 4 warp grid, 32x32 tiles
    int row0 = blockIdx.x * 128;
    int colbase0 = blockIdx.y * 4096;

    stage_tile(sAc, g_F1h + (size_t)row0 * DD, tid);
    stage_tile_cp(sbB[0], g_F1h + (size_t)colbase0 * DD, tid);
    CP_COMMIT();

    float tv[8];
    int ti[8];
#pragma unroll
    for (int q = 0; q < 8; q++) { tv[q] = -1e30f; ti[q] = 0; }

    uint32_t aBase = sbA + (uint32_t)(warp_m * 32 + (lane & 15)) * (HP * 2)
                   + (uint32_t)(lane >> 4) * 16;
    uint32_t bFragOff = (uint32_t)(warp_n * 32 + ((lane >> 4) << 3) + (lane & 7)) * (HP * 2)
                      + (uint32_t)((lane >> 3) & 1) * 16;
    int srow = tid & 127, shalf = (tid >> 7) & 1;   // scan mapping (threads 0-255)

    for (int t = 0; t < 32; t++) {
        int buf = t & 1;
        if (t + 1 < 32) {
            stage_tile_cp(sbB[buf ^ 1],
                          g_F1h + (size_t)(colbase0 + (t + 1) * 128) * DD, tid);
            CP_COMMIT();
            CP_WAIT(1);
        } else {
            CP_WAIT(0);
        }
        __syncthreads();

        float acc[2][4][4];
#pragma unroll
        for (int mt = 0; mt < 2; mt++)
#pragma unroll
            for (int g = 0; g < 4; g++)
#pragma unroll
                for (int e = 0; e < 4; e++) acc[mt][g][e] = 0.f;

        uint32_t bB = sbB[buf] + bFragOff;
#pragma unroll 1
        for (int ks = 0; ks < 16; ks++) {
            uint32_t a[2][4], b[2][4];
            ldmx4(a[0], aBase + ks * 32);
            ldmx4(a[1], aBase + 16 * (HP * 2) + ks * 32);
            ldmx4(b[0], bB + ks * 32);
            ldmx4(b[1], bB + 16 * (HP * 2) + ks * 32);
#pragma unroll
            for (int mt = 0; mt < 2; mt++)
#pragma unroll
                for (int nf = 0; nf < 2; nf++) {
                    mma_bf16(acc[mt][nf * 2 + 0], a[mt], b[nf][0], b[nf][1]);
                    mma_bf16(acc[mt][nf * 2 + 1], a[mt], b[nf][2], b[nf][3]);
                }
        }
        __syncthreads();     // compute done; sB[buf] reusable as C

        float* sC = (float*)sBc[buf];
#pragma unroll
        for (int mt = 0; mt < 2; mt++) {
            int rb = warp_m * 32 + mt * 16 + (lane >> 2);
#pragma unroll
            for (int g = 0; g < 4; g++) {
                int cb = warp_n * 32 + (g >> 1) * 16 + (g & 1) * 8 + (lane & 3) * 2;
                sC[cb * PCC + rb]           = acc[mt][g][0];
                sC[(cb + 1) * PCC + rb]     = acc[mt][g][1];
                sC[cb * PCC + rb + 8]       = acc[mt][g][2];
                sC[(cb + 1) * PCC + rb + 8] = acc[mt][g][3];
            }
        }
        __syncthreads();

        if (tid < 256) {
            int colb = colbase0 + t * 128 + shalf * 64;
            const float* base = sC + (shalf * 64) * PCC + srow;
#pragma unroll 4
            for (int c = 0; c < 64; c++) {
                float v = base[c * PCC];
                if (v > tv[7]) {
                    tv[7] = v; ti[7] = colb + c;
                    TS8(7) TS8(6) TS8(5) TS8(4) TS8(3) TS8(2) TS8(1)
                }
            }
        }
        __syncthreads();
    }
    if (tid < 256) {
        int r = row0 + srow;
        int base = blockIdx.y * 16 + shalf * 8;
#pragma unroll
        for (int q = 0; q < 8; q++)
            g_ci[(size_t)r * NC + base + q] = ti[q];
    }
}

// ---------------- kernel 5: W_out projection ---------------------------------
__global__ void __launch_bounds__(256, 1)
k_projO(const float* __restrict__ Wo, const float* __restrict__ bo) {
    extern __shared__ float sm[];
    float* sA = sm;
    float* sW = sm + 256 * PA;
    int tid = threadIdx.x, tx = tid & 15, ty = tid >> 4;
    int c0 = blockIdx.x * 128, row0 = blockIdx.y * 64;

    for (int i = tid; i < 256 * 16; i += 256) {
        int mc = i & 15, k = i >> 4;
        *(float4*)(sA + k * PA + mc * 4) = *(const float4*)(g_HnT + (size_t)k * NN + row0 + mc * 4);
    }
    for (int i = tid; i < 256 * 32; i += 256) {
        int cc = i & 31, k = i >> 5;
        *(float4*)(sW + k * PB + cc * 4) = *(const float4*)(Wo + k * 256 + c0 + cc * 4);
    }
    __syncthreads();

    ull acc[4][4];
#pragma unroll
    for (int m = 0; m < 4; m++)
#pragma unroll
        for (int p = 0; p < 4; p++) acc[m][p] = 0ull;
    mma_64x128(sA, sW, acc, tx, ty);

#pragma unroll
    for (int m = 0; m < 4; m++) {
        int r = row0 + ty * 4 + m;
#pragma unroll
        for (int g = 0; g < 2; g++) {
            int cg = c0 + g * 64 + tx * 4;
            float4 o;
            o.x = lo32(acc[m][2 * g + 0]) + bo[cg + 0];
            o.y = hi32(acc[m][2 * g + 0]) + bo[cg + 1];
            o.z = lo32(acc[m][2 * g + 1]) + bo[cg + 2];
            o.w = hi32(acc[m][2 * g + 1]) + bo[cg + 3];
            *(float4*)(g_B + (size_t)r * DD + cg) = o;
        }
    }
}

// ---------------- kernel 6: zero A region ------------------------------------
__global__ void k_zeroA(float* __restrict__ A) {
    size_t i = (size_t)blockIdx.x * blockDim.x + threadIdx.x;
    size_t total = (size_t)NN * NN / 4;
    float4 z = make_float4(0.f, 0.f, 0.f, 0.f);
    for (; i < total; i += (size_t)gridDim.x * blockDim.x) ((float4*)A)[i] = z;
}

// ---------------- A(d) ----------------
__device__ __forceinline__ float A32(float d) {
    d = fminf(fmaxf(d, -1.f), 1.f);
    float sam = acosf(d);
    float z = expf(-0.2f * sam);
    float s = 1.f / (1.f + expf(-z));
    return fmaxf(s, 0.1f);
}

// sorting-network comparator: order by index ascending
#define CMPIX(a, b) do { \
    if (ki[a] > ki[b]) { int _t = ki[a]; ki[a] = ki[b]; ki[b] = _t; \
                         float _v = kv[a]; kv[a] = kv[b]; kv[b] = _v; } \
} while (0)

// ---------------- kernel 7: rerank (compensated dots + warp-parallel select) -
__global__ void __launch_bounds__(256) k_rerank(float* __restrict__ Aout) {
    int i = blockIdx.x;
    int t = threadIdx.x;
    int cand = t >> 3, chunk = t & 7;
    __shared__ float ssum[NC][8], scmp[NC][8];
    __shared__ int sci[NC];
    __shared__ float sdv[NC];
    if (t < NC) sci[t] = g_ci[(size_t)i * NC + t];
    __syncthreads();
    int j = sci[cand];
    const float* fi = g_F1 + (size_t)i * DD + chunk * 32;
    const float* fj = g_F1 + (size_t)j * DD + chunk * 32;
    float s = 0.f, comp = 0.f;
#pragma unroll
    for (int k = 0; k < 32; k += 4) {
        float4 a = *(const float4*)(fi + k);
        float4 b = *(const float4*)(fj + k);
        float av[4] = {a.x, a.y, a.z, a.w};
        float bv[4] = {b.x, b.y, b.z, b.w};
#pragma unroll
        for (int e = 0; e < 4; e++) {
            float p  = __fmul_rn(av[e], bv[e]);
            float e1 = __fmaf_rn(av[e], bv[e], -p);
            float tt = __fadd_rn(s, p);
            float bb = __fsub_rn(tt, s);
            float e2 = __fadd_rn(__fsub_rn(s, __fsub_rn(tt, bb)), __fsub_rn(p, bb));
            s = tt;
            comp = __fadd_rn(comp, __fadd_rn(e1, e2));
        }
    }
    ssum[cand][chunk] = s;
    scmp[cand][chunk] = comp;
    __syncthreads();
    if (t < NC) {
        float S = 0.f, C = 0.f;
#pragma unroll
        for (int c = 0; c < 8; c++) {
            float p  = ssum[t][c];
            float tt = __fadd_rn(S, p);
            float bb = __fsub_rn(tt, S);
            float e2 = __fadd_rn(__fsub_rn(S, __fsub_rn(tt, bb)), __fsub_rn(p, bb));
            S = tt;
            C = __fadd_rn(C, __fadd_rn(scmp[t][c], e2));
        }
        sdv[t] = __fadd_rn(S, C);
    }
    __syncthreads();
    // warp 0: parallel top-5 selection (A desc, index asc), 1 candidate/lane
    if (t < 32) {
        float v = A32(sdv[t]);
        int idx = sci[t];
        float selv[KTOP]; int seli[KTOP];
#pragma unroll
        for (int s5 = 0; s5 < KTOP; s5++) {
            float bv = v; int bi = idx;
#pragma unroll
            for (int o = 16; o; o >>= 1) {
                float ov = __shfl_xor_sync(0xffffffffu, bv, o);
                int oi = __shfl_xor_sync(0xffffffffu, bi, o);
                if (ov > bv || (ov == bv && oi < bi)) { bv = ov; bi = oi; }
            }
            selv[s5] = bv; seli[s5] = bi;
            if (idx == bi) v = -1e30f;    // indices are distinct -> exact removal
        }
        if (t == 0) {
            int ki[KTOP]; float kv[KTOP];
#pragma unroll
            for (int q = 0; q < KTOP; q++) { ki[q] = seli[q]; kv[q] = selv[q]; }
            // 9-comparator sorting network for n=5, ascending index
            CMPIX(0, 1); CMPIX(3, 4); CMPIX(2, 4); CMPIX(2, 3); CMPIX(0, 3);
            CMPIX(0, 2); CMPIX(1, 4); CMPIX(1, 3); CMPIX(1, 2);
            float sum = 0.f;
#pragma unroll
            for (int q = 0; q < KTOP; q++) {
                sum = __fadd_rn(sum, kv[q]);
                g_topi[i * KTOP + q] = ki[q];
                g_av[i * KTOP + q] = kv[q];
                if (Aout) Aout[(size_t)i * NN + ki[q]] = kv[q];
            }
            g_dinv[i] = rsqrtf(sum);
        }
    }
}

// ---------------- kernel 8: out ----------------------------------------------
__global__ void k_out(float* __restrict__ out) {
    int wid = threadIdx.x >> 5, lane = threadIdx.x & 31;
    int i = blockIdx.x * 8 + wid;
    float di = g_dinv[i];
    float a0[8] = {0.f, 0.f, 0.f, 0.f, 0.f, 0.f, 0.f, 0.f};
#pragma unroll
    for (int s = 0; s < KTOP; s++) {
        int j = g_topi[i * KTOP + s];
        float c = di * g_av[i * KTOP + s] * g_dinv[j];
        float4 b0 = *(const float4*)(g_B + (size_t)j * DD + lane * 4);
        float4 b1 = *(const float4*)(g_B + (size_t)j * DD + 128 + lane * 4);
        a0[0] = __fmaf_rn(c, b0.x, a0[0]); a0[1] = __fmaf_rn(c, b0.y, a0[1]);
        a0[2] = __fmaf_rn(c, b0.z, a0[2]); a0[3] = __fmaf_rn(c, b0.w, a0[3]);
        a0[4] = __fmaf_rn(c, b1.x, a0[4]); a0[5] = __fmaf_rn(c, b1.y, a0[5]);
        a0[6] = __fmaf_rn(c, b1.z, a0[6]); a0[7] = __fmaf_rn(c, b1.w, a0[7]);
    }
#pragma unroll
    for (int q = 0; q < 8; q++)
        a0[q] = (a0[q] >= 0.f) ? a0[q] : 0.01f * a0[q];
    *(float4*)(out + (size_t)i * DD + lane * 4) = make_float4(a0[0], a0[1], a0[2], a0[3]);
    *(float4*)(out + (size_t)i * DD + 128 + lane * 4) = make_float4(a0[4], a0[5], a0[6], a0[7]);
}

// ---------------- launch -----------------------------------------------------
extern "C" void kernel_launch(void* const* d_in, const int* in_sizes, int n_in,
                              void* d_out, int out_size) {
    const float* H     = (const float*)d_in[0];
    const float* gamma = (const float*)d_in[1];
    const float* beta  = (const float*)d_in[2];
    const float* Wt    = (const float*)d_in[3];
    const float* bt    = (const float*)d_in[4];
    const float* Wo    = (const float*)d_in[5];
    const float* bo    = (const float*)d_in[6];

    float* outp = (float*)d_out;
    float* Aout = ((size_t)out_size >= (size_t)NN * DD + (size_t)NN * NN)
                  ? outp + (size_t)NN * DD : nullptr;

    cudaFuncSetAttribute(k_projT, cudaFuncAttributeMaxDynamicSharedMemorySize, SMEMT_BYTES);
    cudaFuncSetAttribute(k_projO, cudaFuncAttributeMaxDynamicSharedMemorySize, SMEM_BYTES);
    cudaFuncSetAttribute(k_aff, cudaFuncAttributeMaxDynamicSharedMemorySize, AFF_SMEM);

    k_stats<<<DD / 32, 256>>>(H, gamma, beta);                       // 0
    { dim3 b(32, 8), g(DD / 32, NN / 32); k_bnT<<<g, b>>>(H); }      // 1
    k_projT<<<NN / 64, 256, SMEMT_BYTES>>>(Wt, bt);                  // 2
    { dim3 g(NN / 128, 2); k_aff<<<g, AFF_T, AFF_SMEM>>>(); }        // 3  <- ncu slot
    { dim3 g(2, NN / 64); k_projO<<<g, 256, SMEM_BYTES>>>(Wo, bo); } // 4
    if (Aout) k_zeroA<<<2048, 256>>>(Aout);                          // 5
    k_rerank<<<NN, 256>>>(Aout);                                     // 6
    k_out<<<NN / 8, 256>>>(outp);                                    // 7
}